// round 5
// baseline (speedup 1.0000x reference)
#include <cuda_runtime.h>

#define T_DIM 3
#define B_DIM 100000
#define D_DIM 128
#define NEG_SLOPE 0.01f
#define TOTAL_ROWS (T_DIM * B_DIM)

// Persistent grid-stride kernel: one warp per (t,b) row per iteration.
// Single pass over all inputs; every byte touched exactly once.
__global__ __launch_bounds__(256, 8)
void attconv_kernel(const float4* __restrict__ h_center,   // (T*B*32) float4
                    const float4* __restrict__ h_neigh,    // (T*T*B*32) float4
                    const float4* __restrict__ att_w,      // (T*64) float4
                    const float*  __restrict__ att_b,      // (T)
                    float4* __restrict__ out)              // (T*B*32) float4
{
    const int lane   = threadIdx.x & 31;
    const int warp0  = (blockIdx.x * blockDim.x + threadIdx.x) >> 5;
    const int nwarps = (gridDim.x * blockDim.x) >> 5;

    for (int row = warp0; row < TOTAL_ROWS; row += nwarps) {
        const int t = row / B_DIM;
        const int b = row - t * B_DIM;

        const int ctr_off = row * 32 + lane;
        const int nb_base = (t * T_DIM * B_DIM + b) * 32 + lane;

        // Issue all independent loads up front (MLP=6 per lane). Streaming
        // (evict-first) for the big tensors: zero reuse.
        const float4 ch = __ldcs(h_center + ctr_off);
        const float4 n0 = __ldcs(h_neigh + nb_base + 0 * B_DIM * 32);
        const float4 n1 = __ldcs(h_neigh + nb_base + 1 * B_DIM * 32);
        const float4 n2 = __ldcs(h_neigh + nb_base + 2 * B_DIM * 32);
        const float4 wh = __ldg(att_w + t * 64 + lane);
        const float4 we = __ldg(att_w + t * 64 + 32 + lane);
        const float bias = __ldg(att_b + t);

        // Per-lane partials; fold the score_h partial into each neighbor
        // partial so only 4 reductions are needed:
        //   sum(p_n + ph_lane) = P_n + PH  (exactly the reference's p_n + ph).
        float ph = ch.x * wh.x + ch.y * wh.y + ch.z * wh.z + ch.w * wh.w;
        float p0 = n0.x * we.x + n0.y * we.y + n0.z * we.z + n0.w * we.w + ph;
        float p1 = n1.x * we.x + n1.y * we.y + n1.z * we.z + n1.w * we.w + ph;
        float p2 = n2.x * we.x + n2.y * we.y + n2.z * we.z + n2.w * we.w + ph;
        float p3 = ch.x * we.x + ch.y * we.y + ch.z * we.z + ch.w * we.w + ph;

        // Warp-wide butterfly reduction of the 4 folded partials.
        #pragma unroll
        for (int off = 16; off > 0; off >>= 1) {
            p0 += __shfl_xor_sync(0xFFFFFFFFu, p0, off);
            p1 += __shfl_xor_sync(0xFFFFFFFFu, p1, off);
            p2 += __shfl_xor_sync(0xFFFFFFFFu, p2, off);
            p3 += __shfl_xor_sync(0xFFFFFFFFu, p3, off);
        }

        float s0 = p0 + bias;
        float s1 = p1 + bias;
        float s2 = p2 + bias;
        float s3 = p3 + bias;

        // LeakyReLU.
        s0 = (s0 >= 0.f) ? s0 : NEG_SLOPE * s0;
        s1 = (s1 >= 0.f) ? s1 : NEG_SLOPE * s1;
        s2 = (s2 >= 0.f) ? s2 : NEG_SLOPE * s2;
        s3 = (s3 >= 0.f) ? s3 : NEG_SLOPE * s3;

        // Softmax over 4 candidates (n0, n1, n2, center).
        float m = fmaxf(fmaxf(s0, s1), fmaxf(s2, s3));
        float e0 = __expf(s0 - m);
        float e1 = __expf(s1 - m);
        float e2 = __expf(s2 - m);
        float e3 = __expf(s3 - m);
        float inv = 1.0f / (e0 + e1 + e2 + e3);
        float a0 = e0 * inv, a1 = e1 * inv, a2 = e2 * inv, a3 = e3 * inv;

        float4 o;
        o.x = a0 * n0.x + a1 * n1.x + a2 * n2.x + a3 * ch.x;
        o.y = a0 * n0.y + a1 * n1.y + a2 * n2.y + a3 * ch.y;
        o.z = a0 * n0.z + a1 * n1.z + a2 * n2.z + a3 * ch.z;
        o.w = a0 * n0.w + a1 * n1.w + a2 * n2.w + a3 * ch.w;

        __stcs(out + ctr_off, o);
    }
}

extern "C" void kernel_launch(void* const* d_in, const int* in_sizes, int n_in,
                              void* d_out, int out_size) {
    const float4* h_center = (const float4*)d_in[0];
    const float4* h_neigh  = (const float4*)d_in[1];
    const float4* att_w    = (const float4*)d_in[2];
    const float*  att_b    = (const float*)d_in[3];
    float4* out = (float4*)d_out;

    // Persistent grid: 8 CTAs of 256 threads per SM (full occupancy at 32 regs),
    // 148+ SMs -> 1184 CTAs; each warp grid-strides over ~32 rows.
    const int threads = 256;
    const int blocks  = 1184;

    attconv_kernel<<<blocks, threads>>>(h_center, h_neigh, att_w, att_b, out);
}

// round 6
// speedup vs baseline: 1.0824x; 1.0824x over previous
#include <cuda_runtime.h>

#define T_DIM 3
#define B_DIM 100000
#define D_DIM 128
#define NEG_SLOPE 0.01f

// One warp per (t, b) row, one-shot grid (CTA churn keeps the memory pipe
// full). D=128 -> each lane owns 4 consecutive floats (float4). Single pass:
// every input byte touched exactly once. score_h partial is folded into each
// neighbor partial so only 4 warp reductions are needed (20 SHFL, not 25).
__global__ __launch_bounds__(256, 8)
void attconv_kernel(const float4* __restrict__ h_center,   // (T*B*32) float4
                    const float4* __restrict__ h_neigh,    // (T*T*B*32) float4
                    const float4* __restrict__ att_w,      // (T*64) float4
                    const float*  __restrict__ att_b,      // (T)
                    float4* __restrict__ out)              // (T*B*32) float4
{
    const int gwarp = (blockIdx.x * blockDim.x + threadIdx.x) >> 5;  // = t*B + b
    const int lane  = threadIdx.x & 31;
    if (gwarp >= T_DIM * B_DIM) return;

    const int t = gwarp / B_DIM;
    const int b = gwarp - t * B_DIM;

    // float4-granular offsets (32 float4 per row of 128 floats)
    const int ctr_off = gwarp * 32 + lane;
    const int nb_base = (t * T_DIM * B_DIM + b) * 32 + lane;

    // Issue all independent loads up front (MLP=6 per lane).
    const float4 ch = __ldg(h_center + ctr_off);
    const float4 n0 = __ldg(h_neigh + nb_base + 0 * B_DIM * 32);
    const float4 n1 = __ldg(h_neigh + nb_base + 1 * B_DIM * 32);
    const float4 n2 = __ldg(h_neigh + nb_base + 2 * B_DIM * 32);
    const float4 wh = __ldg(att_w + t * 64 + lane);        // w_h chunk
    const float4 we = __ldg(att_w + t * 64 + 32 + lane);   // w_e chunk
    const float bias = __ldg(att_b + t);

    // Per-lane partials with score_h folded in: sum(p_n + ph_lane) = P_n + PH.
    float ph = ch.x * wh.x + ch.y * wh.y + ch.z * wh.z + ch.w * wh.w;
    float p0 = n0.x * we.x + n0.y * we.y + n0.z * we.z + n0.w * we.w + ph;
    float p1 = n1.x * we.x + n1.y * we.y + n1.z * we.z + n1.w * we.w + ph;
    float p2 = n2.x * we.x + n2.y * we.y + n2.z * we.z + n2.w * we.w + ph;
    float p3 = ch.x * we.x + ch.y * we.y + ch.z * we.z + ch.w * we.w + ph;

    // Warp-wide butterfly reduction of the 4 folded partials.
    #pragma unroll
    for (int off = 16; off > 0; off >>= 1) {
        p0 += __shfl_xor_sync(0xFFFFFFFFu, p0, off);
        p1 += __shfl_xor_sync(0xFFFFFFFFu, p1, off);
        p2 += __shfl_xor_sync(0xFFFFFFFFu, p2, off);
        p3 += __shfl_xor_sync(0xFFFFFFFFu, p3, off);
    }

    // scores = folded sum + bias, then LeakyReLU.
    float s0 = p0 + bias;
    float s1 = p1 + bias;
    float s2 = p2 + bias;
    float s3 = p3 + bias;
    s0 = (s0 >= 0.f) ? s0 : NEG_SLOPE * s0;
    s1 = (s1 >= 0.f) ? s1 : NEG_SLOPE * s1;
    s2 = (s2 >= 0.f) ? s2 : NEG_SLOPE * s2;
    s3 = (s3 >= 0.f) ? s3 : NEG_SLOPE * s3;

    // Softmax over the 4 candidates (neighbors 0..2, center last).
    float m = fmaxf(fmaxf(s0, s1), fmaxf(s2, s3));
    float e0 = __expf(s0 - m);
    float e1 = __expf(s1 - m);
    float e2 = __expf(s2 - m);
    float e3 = __expf(s3 - m);
    float inv = 1.0f / (e0 + e1 + e2 + e3);
    float a0 = e0 * inv, a1 = e1 * inv, a2 = e2 * inv, a3 = e3 * inv;

    // Weighted sum (emd order: [n0, n1, n2, center]).
    float4 o;
    o.x = a0 * n0.x + a1 * n1.x + a2 * n2.x + a3 * ch.x;
    o.y = a0 * n0.y + a1 * n1.y + a2 * n2.y + a3 * ch.y;
    o.z = a0 * n0.z + a1 * n1.z + a2 * n2.z + a3 * ch.z;
    o.w = a0 * n0.w + a1 * n1.w + a2 * n2.w + a3 * ch.w;

    out[ctr_off] = o;
}

extern "C" void kernel_launch(void* const* d_in, const int* in_sizes, int n_in,
                              void* d_out, int out_size) {
    const float4* h_center = (const float4*)d_in[0];
    const float4* h_neigh  = (const float4*)d_in[1];
    const float4* att_w    = (const float4*)d_in[2];
    const float*  att_b    = (const float*)d_in[3];
    float4* out = (float4*)d_out;

    const int total_warps = T_DIM * B_DIM;              // 300000
    const int threads = 256;                            // 8 warps/block
    const int blocks = (total_warps * 32 + threads - 1) / threads;  // 37500

    attconv_kernel<<<blocks, threads>>>(h_center, h_neigh, att_w, att_b, out);
}

// round 7
// speedup vs baseline: 1.0877x; 1.0049x over previous
#include <cuda_runtime.h>

#define T_DIM 3
#define B_DIM 100000
#define D_DIM 128
#define NEG_SLOPE 0.01f
#define TOTAL_ROWS (T_DIM * B_DIM)

// One warp per PAIR of consecutive (t,b) rows, one-shot grid. Each lane owns
// one float4 of each row. Per stream each warp now covers 1KB contiguous
// (2 rows x 512B) and holds 12 outstanding loads, improving HBM burst/row-
// buffer locality and latency tolerance. B_DIM is even, so a pair never
// straddles a t boundary (weights/bias shared within the pair).
__global__ __launch_bounds__(256, 4)
void attconv_kernel(const float4* __restrict__ h_center,   // (T*B*32) float4
                    const float4* __restrict__ h_neigh,    // (T*T*B*32) float4
                    const float4* __restrict__ att_w,      // (T*64) float4
                    const float*  __restrict__ att_b,      // (T)
                    float4* __restrict__ out)              // (T*B*32) float4
{
    const int gwarp = (blockIdx.x * blockDim.x + threadIdx.x) >> 5;
    const int lane  = threadIdx.x & 31;
    const int row0  = gwarp * 2;                 // first row of the pair
    if (row0 >= TOTAL_ROWS) return;

    const int t  = row0 / B_DIM;                 // same t for both rows
    const int b0 = row0 - t * B_DIM;

    const int ctr0 = row0 * 32 + lane;                         // row0 center
    const int nb0  = (t * T_DIM * B_DIM + b0) * 32 + lane;     // row0 neigh base
    // row1 offsets are +32 float4 in every stream.

    // Issue all 12 big loads up front (plus weights).
    const float4 ca = __ldg(h_center + ctr0);
    const float4 cb = __ldg(h_center + ctr0 + 32);
    const float4 a0 = __ldg(h_neigh + nb0 + 0 * B_DIM * 32);
    const float4 b0v= __ldg(h_neigh + nb0 + 0 * B_DIM * 32 + 32);
    const float4 a1 = __ldg(h_neigh + nb0 + 1 * B_DIM * 32);
    const float4 b1v= __ldg(h_neigh + nb0 + 1 * B_DIM * 32 + 32);
    const float4 a2 = __ldg(h_neigh + nb0 + 2 * B_DIM * 32);
    const float4 b2v= __ldg(h_neigh + nb0 + 2 * B_DIM * 32 + 32);
    const float4 wh = __ldg(att_w + t * 64 + lane);
    const float4 we = __ldg(att_w + t * 64 + 32 + lane);
    const float bias = __ldg(att_b + t);

    // ---- row 0 partials (score_h folded in) ----
    float pha = ca.x * wh.x + ca.y * wh.y + ca.z * wh.z + ca.w * wh.w;
    float pa0 = a0.x * we.x + a0.y * we.y + a0.z * we.z + a0.w * we.w + pha;
    float pa1 = a1.x * we.x + a1.y * we.y + a1.z * we.z + a1.w * we.w + pha;
    float pa2 = a2.x * we.x + a2.y * we.y + a2.z * we.z + a2.w * we.w + pha;
    float pa3 = ca.x * we.x + ca.y * we.y + ca.z * we.z + ca.w * we.w + pha;
    // ---- row 1 partials ----
    float phb = cb.x * wh.x + cb.y * wh.y + cb.z * wh.z + cb.w * wh.w;
    float pb0 = b0v.x * we.x + b0v.y * we.y + b0v.z * we.z + b0v.w * we.w + phb;
    float pb1 = b1v.x * we.x + b1v.y * we.y + b1v.z * we.z + b1v.w * we.w + phb;
    float pb2 = b2v.x * we.x + b2v.y * we.y + b2v.z * we.z + b2v.w * we.w + phb;
    float pb3 = cb.x * we.x + cb.y * we.y + cb.z * we.z + cb.w * we.w + phb;

    // 8 butterfly reductions, interleaved for ILP.
    #pragma unroll
    for (int off = 16; off > 0; off >>= 1) {
        pa0 += __shfl_xor_sync(0xFFFFFFFFu, pa0, off);
        pa1 += __shfl_xor_sync(0xFFFFFFFFu, pa1, off);
        pa2 += __shfl_xor_sync(0xFFFFFFFFu, pa2, off);
        pa3 += __shfl_xor_sync(0xFFFFFFFFu, pa3, off);
        pb0 += __shfl_xor_sync(0xFFFFFFFFu, pb0, off);
        pb1 += __shfl_xor_sync(0xFFFFFFFFu, pb1, off);
        pb2 += __shfl_xor_sync(0xFFFFFFFFu, pb2, off);
        pb3 += __shfl_xor_sync(0xFFFFFFFFu, pb3, off);
    }

    // ---- row 0 softmax + output ----
    {
        float s0 = pa0 + bias, s1 = pa1 + bias, s2 = pa2 + bias, s3 = pa3 + bias;
        s0 = (s0 >= 0.f) ? s0 : NEG_SLOPE * s0;
        s1 = (s1 >= 0.f) ? s1 : NEG_SLOPE * s1;
        s2 = (s2 >= 0.f) ? s2 : NEG_SLOPE * s2;
        s3 = (s3 >= 0.f) ? s3 : NEG_SLOPE * s3;
        float m = fmaxf(fmaxf(s0, s1), fmaxf(s2, s3));
        float e0 = __expf(s0 - m), e1 = __expf(s1 - m);
        float e2 = __expf(s2 - m), e3 = __expf(s3 - m);
        float inv = 1.0f / (e0 + e1 + e2 + e3);
        float w0 = e0 * inv, w1 = e1 * inv, w2 = e2 * inv, w3 = e3 * inv;
        float4 o;
        o.x = w0 * a0.x + w1 * a1.x + w2 * a2.x + w3 * ca.x;
        o.y = w0 * a0.y + w1 * a1.y + w2 * a2.y + w3 * ca.y;
        o.z = w0 * a0.z + w1 * a1.z + w2 * a2.z + w3 * ca.z;
        o.w = w0 * a0.w + w1 * a1.w + w2 * a2.w + w3 * ca.w;
        out[ctr0] = o;
    }
    // ---- row 1 softmax + output ----
    {
        float s0 = pb0 + bias, s1 = pb1 + bias, s2 = pb2 + bias, s3 = pb3 + bias;
        s0 = (s0 >= 0.f) ? s0 : NEG_SLOPE * s0;
        s1 = (s1 >= 0.f) ? s1 : NEG_SLOPE * s1;
        s2 = (s2 >= 0.f) ? s2 : NEG_SLOPE * s2;
        s3 = (s3 >= 0.f) ? s3 : NEG_SLOPE * s3;
        float m = fmaxf(fmaxf(s0, s1), fmaxf(s2, s3));
        float e0 = __expf(s0 - m), e1 = __expf(s1 - m);
        float e2 = __expf(s2 - m), e3 = __expf(s3 - m);
        float inv = 1.0f / (e0 + e1 + e2 + e3);
        float w0 = e0 * inv, w1 = e1 * inv, w2 = e2 * inv, w3 = e3 * inv;
        float4 o;
        o.x = w0 * b0v.x + w1 * b1v.x + w2 * b2v.x + w3 * cb.x;
        o.y = w0 * b0v.y + w1 * b1v.y + w2 * b2v.y + w3 * cb.y;
        o.z = w0 * b0v.z + w1 * b1v.z + w2 * b2v.z + w3 * cb.z;
        o.w = w0 * b0v.w + w1 * b1v.w + w2 * b2v.w + w3 * cb.w;
        out[ctr0 + 32] = o;
    }
}

extern "C" void kernel_launch(void* const* d_in, const int* in_sizes, int n_in,
                              void* d_out, int out_size) {
    const float4* h_center = (const float4*)d_in[0];
    const float4* h_neigh  = (const float4*)d_in[1];
    const float4* att_w    = (const float4*)d_in[2];
    const float*  att_b    = (const float*)d_in[3];
    float4* out = (float4*)d_out;

    const int total_pairs = TOTAL_ROWS / 2;             // 150000 warps
    const int threads = 256;                            // 8 warps/block
    const int blocks = (total_pairs * 32 + threads - 1) / threads;  // 18750

    attconv_kernel<<<blocks, threads>>>(h_center, h_neigh, att_w, att_b, out);
}